// round 14
// baseline (speedup 1.0000x reference)
#include <cuda_runtime.h>
#include <cstdint>

// ---------------------------------------------------------------------------
// DGCNN-style net. B=8, N=4096, K=20. Output: 11 floats.
// Exact fp32. KNN = split-K (4 candidate slices per query, merged with the
// jax.lax.top_k comparator) for 4x thread-level parallelism.
// ---------------------------------------------------------------------------
#define NB 8
#define NN 4096
#define NP (NB * NN)      // 32768
#define KK 20
#define SPLIT 4
#define SLOPE 0.2f
#define MCNT ((double)NP * (double)KK)   // 655360 samples per BN channel

// ------------------------------ device scratch ------------------------------
__device__ int   g_idx1[NP * KK];
__device__ int   g_idx2[NP * KK];
__device__ int   g_idx3[NP * KK];
__device__ float g_nrm[NP];

__device__ float g_pv[NP * SPLIT * KK];   // partial top-k values
__device__ int   g_pi[NP * SPLIT * KK];   // partial top-k indices

__device__ float g_P1[NP * 32], g_Q1[NP * 32];
__device__ float g_ymx1[NP * 32], g_ymn1[NP * 32];
__device__ float g_x1[NP * 32];

__device__ float g_PA[NP * 64], g_PB[NP * 64], g_Q[NP * 64];
__device__ float g_ymx2[NP * 64], g_ymn2[NP * 64];
__device__ float g_x2[NP * 64];

__device__ float g_ymxd1[NP * 64], g_ymnd1[NP * 64];
__device__ float g_ymxd2[NP * 64], g_ymnd2[NP * 64];

__device__ double g_S1[256], g_S2[256];
__device__ float  g_scale[256], g_shift[256];
__device__ double g_hcol[128];

// ------------------------------ helpers -------------------------------------
__device__ __forceinline__ unsigned long long pack2(float a, float b) {
    return (unsigned long long)__float_as_uint(a) |
           ((unsigned long long)__float_as_uint(b) << 32);
}
__device__ __forceinline__ float2 unpack2(unsigned long long v) {
    float2 r;
    r.x = __uint_as_float((unsigned int)v);
    r.y = __uint_as_float((unsigned int)(v >> 32));
    return r;
}
#define FMA2(acc, a, b) \
    asm("fma.rn.f32x2 %0, %1, %2, %0;" : "+l"(acc) : "l"(a), "l"(b))

__device__ __forceinline__ float lrelu(float v) { return v >= 0.f ? v : SLOPE * v; }

// ------------------------------ zero accumulators ----------------------------
__global__ void zero_kernel() {
    int t = threadIdx.x;
    if (t < 256) { g_S1[t] = 0.0; g_S2[t] = 0.0; }
    if (t < 128) g_hcol[t] = 0.0;
}

// ------------------------------ point squared norms --------------------------
// feat(b,n,c) at feat[b*bs + n*ps + c*cs]
__global__ void norm_kernel(const float* __restrict__ feat, int ps, int cs, int bs,
                            int C, float* __restrict__ out) {
    int pt = blockIdx.x * blockDim.x + threadIdx.x;
    if (pt >= NP) return;
    int b = pt >> 12, n = pt & (NN - 1);
    const float* f = feat + (size_t)b * bs + (size_t)n * ps;
    float s = 0.f;
    for (int c = 0; c < C; c++) { float v = f[(size_t)c * cs]; s = fmaf(v, v, s); }
    out[pt] = s;
}

// ------------------------------ split-K exact KNN ----------------------------
// rank by e = 2<q,m> - |m|^2 (same ordering as reference d per query).
// Each z-slice scans NN/SPLIT candidates; partial list sorted desc-val/asc-idx.
template <int C>
__global__ void __launch_bounds__(128)
knn_part(const float* __restrict__ feat, int ps, int cs, int bs,
         const float* __restrict__ norms,
         float* __restrict__ pvOut, int* __restrict__ piOut) {
    constexpr int CP = (C + 3) & ~3;
    constexpr int TILE = 128;
    constexpr int SLICE = NN / SPLIT;
    __shared__ __align__(16) float st[TILE * CP];
    __shared__ float sn[TILE];

    const int b  = blockIdx.y;
    const int z  = blockIdx.z;
    const int qn = blockIdx.x * TILE + threadIdx.x;
    const float* fb = feat + (size_t)b * bs;
    const float* nb = norms + b * NN;

    unsigned long long qp[CP / 2];
#pragma unroll
    for (int j = 0; j < CP / 2; j++) {
        float a  = (2 * j     < C) ? fb[(size_t)qn * ps + (size_t)(2 * j) * cs]     : 0.f;
        float c2 = (2 * j + 1 < C) ? fb[(size_t)qn * ps + (size_t)(2 * j + 1) * cs] : 0.f;
        qp[j] = pack2(a, c2);
    }

    const float NEGINF = __int_as_float(0xff800000);
    float kd[KK]; int ki[KK];
#pragma unroll
    for (int i = 0; i < KK; i++) { kd[i] = NEGINF; ki[i] = 0x7fffffff; }
    float curmin = NEGINF; int minpos = 0;

    for (int m0 = z * SLICE; m0 < (z + 1) * SLICE; m0 += TILE) {
        __syncthreads();
#pragma unroll
        for (int i = 0; i < (TILE * CP) / 128; i++) {
            int lin = threadIdx.x + i * 128;
            int m = lin / CP, c = lin % CP;
            st[lin] = (c < C) ? fb[(size_t)(m0 + m) * ps + (size_t)c * cs] : 0.f;
        }
        sn[threadIdx.x] = nb[m0 + threadIdx.x];
        __syncthreads();

#pragma unroll 1
        for (int mm = 0; mm < TILE; mm++) {
            unsigned long long a0 = 0ull, a1 = 0ull;
            const ulonglong2* sp = reinterpret_cast<const ulonglong2*>(st + mm * CP);
#pragma unroll
            for (int j = 0; j < CP / 4; j++) {
                ulonglong2 v = sp[j];
                FMA2(a0, qp[2 * j],     v.x);
                FMA2(a1, qp[2 * j + 1], v.y);
            }
            float2 f0 = unpack2(a0), f1 = unpack2(a1);
            float e = fmaf(2.f, (f0.x + f0.y) + (f1.x + f1.y), -sn[mm]);
            if (e > curmin) {                   // strict > : lowest index wins ties
                int m = m0 + mm;
#pragma unroll
                for (int i = 0; i < KK; i++)
                    if (i == minpos) { kd[i] = e; ki[i] = m; }
                curmin = kd[0]; minpos = 0;
#pragma unroll
                for (int i = 1; i < KK; i++)
                    if (kd[i] < curmin) { curmin = kd[i]; minpos = i; }
            }
        }
    }

    // Sort: descending value, ascending index on ties (top_k order).
#pragma unroll
    for (int i = 0; i < KK - 1; i++)
#pragma unroll
        for (int j = i + 1; j < KK; j++) {
            bool sw = (kd[j] > kd[i]) || (kd[j] == kd[i] && ki[j] < ki[i]);
            float td = sw ? kd[j] : kd[i];
            int   ti = sw ? ki[j] : ki[i];
            kd[j] = sw ? kd[i] : kd[j];
            ki[j] = sw ? ki[i] : ki[j];
            kd[i] = td; ki[i] = ti;
        }

    size_t base = ((size_t)(b * NN + qn) * SPLIT + z) * KK;
#pragma unroll
    for (int i = 0; i < KK; i++) { pvOut[base + i] = kd[i]; piOut[base + i] = ki[i]; }
}

// 4-way merge of sorted partials, jax.lax.top_k comparator.
__global__ void knn_merge(const float* __restrict__ pv, const int* __restrict__ pi,
                          int* __restrict__ idxOut) {
    int q = blockIdx.x * blockDim.x + threadIdx.x;
    if (q >= NP) return;
    const float* v  = pv + (size_t)q * SPLIT * KK;
    const int*   ii = pi + (size_t)q * SPLIT * KK;
    int h[SPLIT] = {0, 0, 0, 0};
    int* op = idxOut + (size_t)q * KK;
    const float NEGINF = __int_as_float(0xff800000);
#pragma unroll 1
    for (int r = 0; r < KK; r++) {
        float bv = NEGINF; int bi = 0x7fffffff; int bs = 0;
#pragma unroll
        for (int s = 0; s < SPLIT; s++) {
            if (h[s] < KK) {
                float vv = v[s * KK + h[s]];
                int   vi = ii[s * KK + h[s]];
                if (vv > bv || (vv == bv && vi < bi)) { bv = vv; bi = vi; bs = s; }
            }
        }
        op[r] = bi;
        h[bs]++;
    }
}

// ------------------------------ per-point projections ------------------------
// P[pt][o] = sum_c w[o][wcol+c]              * feat(pt,c)   (neighbor term)
// Q[pt][o] = sum_c (w[o][wcol+C+c]-w[o][wcol+c]) * feat(pt,c)  (+= if accumQ)
__global__ void proj_kernel(const float* __restrict__ feat, int ps, int cs, int bs,
                            const float* __restrict__ w, int wld, int wcol,
                            int C, int O,
                            float* __restrict__ P, float* __restrict__ Q, int accumQ) {
    __shared__ float wa[64 * 64];
    __shared__ float wb[64 * 64];
    for (int lin = threadIdx.x; lin < O * C; lin += blockDim.x) {
        int o = lin / C, c = lin % C;
        float a  = w[o * wld + wcol + c];
        float b2 = w[o * wld + wcol + C + c];
        wa[c * 64 + o] = a;
        wb[c * 64 + o] = b2 - a;
    }
    __syncthreads();
    int o    = threadIdx.x % O;
    int sub  = threadIdx.x / O;
    int subs = blockDim.x / O;
    for (int pt = blockIdx.x * subs + sub; pt < NP; pt += gridDim.x * subs) {
        int b = pt >> 12, n = pt & (NN - 1);
        const float* f = feat + (size_t)b * bs + (size_t)n * ps;
        float ap = 0.f, aq = 0.f;
        for (int c = 0; c < C; c++) {
            float v = __ldg(f + (size_t)c * cs);
            ap = fmaf(wa[c * 64 + o], v, ap);
            aq = fmaf(wb[c * 64 + o], v, aq);
        }
        P[(size_t)pt * O + o] = ap;
        if (accumQ) Q[(size_t)pt * O + o] += aq;
        else        Q[(size_t)pt * O + o]  = aq;
    }
}

// ------------------------------ edge pass ------------------------------------
// y(pt,o,k) = PA[idxA[k]] (+ PB[idxB[k]]) + Q[pt]; k-th entries paired.
template <int O, bool DUAL>
__global__ void edge_kernel(const int* __restrict__ idxA, const int* __restrict__ idxB,
                            const float* __restrict__ PA, const float* __restrict__ PB,
                            const float* __restrict__ Q,
                            float* __restrict__ YMAX, float* __restrict__ YMIN,
                            double* __restrict__ S1, double* __restrict__ S2) {
    const int t = threadIdx.x;
    const int o = t % O, sub = t / O;
    const int subs = blockDim.x / O;
    const float PINF = __int_as_float(0x7f800000);
    double ds1 = 0.0, ds2 = 0.0;

    for (int pt = blockIdx.x * subs + sub; pt < NP; pt += gridDim.x * subs) {
        const int pbase = pt & ~(NN - 1);
        const int* iA = idxA + (size_t)pt * KK;
        const int* iB = idxB + (size_t)pt * KK;
        float qv = Q[(size_t)pt * O + o];
        float vmax = -PINF, vmin = PINF;
        float ls1 = 0.f, ls2 = 0.f;
#pragma unroll
        for (int k = 0; k < KK; k++) {
            int jA = __ldg(iA + k);
            float v = __ldg(PA + (size_t)(pbase + jA) * O + o);
            if (DUAL) {
                int jB = __ldg(iB + k);
                v += __ldg(PB + (size_t)(pbase + jB) * O + o);
            }
            vmax = fmaxf(vmax, v);
            vmin = fminf(vmin, v);
            float y = v + qv;
            ls1 += y;
            ls2 = fmaf(y, y, ls2);
        }
        YMAX[(size_t)pt * O + o] = vmax + qv;
        YMIN[(size_t)pt * O + o] = vmin + qv;
        ds1 += (double)ls1;
        ds2 += (double)ls2;
    }

    __shared__ double r1[256], r2[256];
    r1[t] = ds1; r2[t] = ds2;
    __syncthreads();
    if (sub == 0) {
        double a = ds1, b2 = ds2;
        for (int s = 1; s < subs; s++) { a += r1[s * O + o]; b2 += r2[s * O + o]; }
        atomicAdd(&S1[o], a);
        atomicAdd(&S2[o], b2);
    }
}

// ------------------------------ BN finalize ----------------------------------
__global__ void finalize_kernel(const double* __restrict__ S1, const double* __restrict__ S2,
                                const float* __restrict__ g, const float* __restrict__ beta,
                                float* __restrict__ scale, float* __restrict__ shift, int O) {
    int o = threadIdx.x;
    if (o >= O) return;
    double mean = S1[o] / MCNT;
    double var  = S2[o] / MCNT - mean * mean;
    double inv  = 1.0 / sqrt(var + 1e-5);
    double sc   = (double)g[o] * inv;
    scale[o] = (float)sc;
    shift[o] = (float)((double)beta[o] - mean * sc);
}

// ------------------------------ apply affine+lrelu to pooled extremum --------
__global__ void apply_kernel(const float* __restrict__ YMAX, const float* __restrict__ YMIN,
                             const float* __restrict__ scale, const float* __restrict__ shift,
                             float* __restrict__ out, int O) {
    int idx = blockIdx.x * blockDim.x + threadIdx.x;
    int o = idx % O;
    float s = scale[o];
    float z = (s >= 0.f) ? YMAX[idx] : YMIN[idx];
    out[idx] = lrelu(fmaf(s, z, shift[o]));
}

// ------------------------------ column sums for the head ---------------------
__global__ void hcol_kernel(const float* __restrict__ mx1, const float* __restrict__ mn1,
                            const float* __restrict__ mx2, const float* __restrict__ mn2) {
    __shared__ float red[256];
    int t = threadIdx.x, o = t & 63, p = t >> 6;
    int pt = blockIdx.x * 4 + p;
    size_t base = (size_t)pt * 64 + o;

    float s1 = g_scale[128 + o], sh1 = g_shift[128 + o];
    float z1 = (s1 >= 0.f) ? mx1[base] : mn1[base];
    float v1 = lrelu(fmaf(s1, z1, sh1));

    float s2 = g_scale[192 + o], sh2 = g_shift[192 + o];
    float z2 = (s2 >= 0.f) ? mx2[base] : mn2[base];
    float v2 = lrelu(fmaf(s2, z2, sh2));

    red[t] = v1 + v2;
    __syncthreads();
    if (o == 0) {
        float s = 0.f;
        for (int j = 0; j < 64; j++) s += red[p * 64 + j];
        atomicAdd(&g_hcol[pt & 127], (double)s);
    }
}

// ------------------------------ tiny MLP head --------------------------------
__global__ void head_kernel(const float* __restrict__ W2d, const float* __restrict__ b2d,
                            const float* __restrict__ W3d, const float* __restrict__ b3d,
                            const float* __restrict__ W4d, const float* __restrict__ b4d,
                            float* __restrict__ out) {
    __shared__ float hm[128], h1[128], h2[64];
    int t = threadIdx.x;
    hm[t] = (float)(g_hcol[t] * (1.0 / 32768.0));
    __syncthreads();
    {
        float a = b2d[t];
        for (int i = 0; i < 128; i++) a = fmaf(W2d[t * 128 + i], hm[i], a);
        h1[t] = lrelu(a);
    }
    __syncthreads();
    if (t < 64) {
        float a = b3d[t];
        for (int i = 0; i < 128; i++) a = fmaf(W3d[t * 128 + i], h1[i], a);
        h2[t] = lrelu(a);
    }
    __syncthreads();
    if (t < 11) {
        float a = b4d[t];
        for (int i = 0; i < 64; i++) a = fmaf(W4d[t * 64 + i], h2[i], a);
        out[t] = lrelu(a);
    }
}

// ------------------------------ launch ---------------------------------------
extern "C" void kernel_launch(void* const* d_in, const int* in_sizes, int n_in,
                              void* d_out, int out_size) {
    const float* x   = (const float*)d_in[0];
    const float* w1  = (const float*)d_in[1];
    const float* g1  = (const float*)d_in[2];
    const float* b1  = (const float*)d_in[3];
    const float* w2  = (const float*)d_in[4];
    const float* g2  = (const float*)d_in[5];
    const float* b2  = (const float*)d_in[6];
    const float* wd1 = (const float*)d_in[7];
    const float* gd1 = (const float*)d_in[8];
    const float* bd1 = (const float*)d_in[9];
    const float* wd2 = (const float*)d_in[10];
    const float* gd2 = (const float*)d_in[11];
    const float* bd2 = (const float*)d_in[12];
    const float* W2d = (const float*)d_in[13];
    const float* b2d = (const float*)d_in[14];
    const float* W3d = (const float*)d_in[15];
    const float* b3d = (const float*)d_in[16];
    const float* W4d = (const float*)d_in[17];
    const float* b4d = (const float*)d_in[18];

    int*    idx1;  cudaGetSymbolAddress((void**)&idx1,  g_idx1);
    int*    idx2;  cudaGetSymbolAddress((void**)&idx2,  g_idx2);
    int*    idx3;  cudaGetSymbolAddress((void**)&idx3,  g_idx3);
    float*  nrm;   cudaGetSymbolAddress((void**)&nrm,   g_nrm);
    float*  pv;    cudaGetSymbolAddress((void**)&pv,    g_pv);
    int*    pi;    cudaGetSymbolAddress((void**)&pi,    g_pi);
    float*  P1;    cudaGetSymbolAddress((void**)&P1,    g_P1);
    float*  Q1;    cudaGetSymbolAddress((void**)&Q1,    g_Q1);
    float*  ymx1;  cudaGetSymbolAddress((void**)&ymx1,  g_ymx1);
    float*  ymn1;  cudaGetSymbolAddress((void**)&ymn1,  g_ymn1);
    float*  x1;    cudaGetSymbolAddress((void**)&x1,    g_x1);
    float*  PA;    cudaGetSymbolAddress((void**)&PA,    g_PA);
    float*  PB;    cudaGetSymbolAddress((void**)&PB,    g_PB);
    float*  Q;     cudaGetSymbolAddress((void**)&Q,     g_Q);
    float*  ymx2;  cudaGetSymbolAddress((void**)&ymx2,  g_ymx2);
    float*  ymn2;  cudaGetSymbolAddress((void**)&ymn2,  g_ymn2);
    float*  x2;    cudaGetSymbolAddress((void**)&x2,    g_x2);
    float*  ymxd1; cudaGetSymbolAddress((void**)&ymxd1, g_ymxd1);
    float*  ymnd1; cudaGetSymbolAddress((void**)&ymnd1, g_ymnd1);
    float*  ymxd2; cudaGetSymbolAddress((void**)&ymxd2, g_ymxd2);
    float*  ymnd2; cudaGetSymbolAddress((void**)&ymnd2, g_ymnd2);
    double* S1;    cudaGetSymbolAddress((void**)&S1,    g_S1);
    double* S2;    cudaGetSymbolAddress((void**)&S2,    g_S2);
    float*  scale; cudaGetSymbolAddress((void**)&scale, g_scale);
    float*  shift; cudaGetSymbolAddress((void**)&shift, g_shift);

    const dim3 kgrid(NN / 128, NB, SPLIT);

    zero_kernel<<<1, 256>>>();

    // -------- layer 1: knn(x, C=3), edge conv 6->32 --------
    norm_kernel<<<NP / 256, 256>>>(x, 1, NN, 3 * NN, 3, nrm);
    knn_part<3><<<kgrid, 128>>>(x, 1, NN, 3 * NN, nrm, pv, pi);
    knn_merge<<<NP / 256, 256>>>(pv, pi, idx1);
    proj_kernel<<<1024, 256>>>(x, 1, NN, 3 * NN, w1, 6, 0, 3, 32, P1, Q1, 0);
    edge_kernel<32, false><<<512, 256>>>(idx1, idx1, P1, P1, Q1, ymx1, ymn1, S1 + 0, S2 + 0);
    finalize_kernel<<<1, 32>>>(S1 + 0, S2 + 0, g1, b1, scale + 0, shift + 0, 32);
    apply_kernel<<<(NP * 32) / 256, 256>>>(ymx1, ymn1, scale + 0, shift + 0, x1, 32);

    // -------- layer 2: knn(x1, C=32), edge conv 70->64 (paired dual gather) --
    norm_kernel<<<NP / 256, 256>>>(x1, 32, 1, NN * 32, 32, nrm);
    knn_part<32><<<kgrid, 128>>>(x1, 32, 1, NN * 32, nrm, pv, pi);
    knn_merge<<<NP / 256, 256>>>(pv, pi, idx2);
    proj_kernel<<<1024, 256>>>(x, 1, NN, 3 * NN, w2, 70, 0, 3, 64, PA, Q, 0);
    proj_kernel<<<1024, 256>>>(x1, 32, 1, NN * 32, w2, 70, 6, 32, 64, PB, Q, 1);
    edge_kernel<64, true><<<512, 256>>>(idx1, idx2, PA, PB, Q, ymx2, ymn2, S1 + 64, S2 + 64);
    finalize_kernel<<<1, 64>>>(S1 + 64, S2 + 64, g2, b2, scale + 64, shift + 64, 64);
    apply_kernel<<<(NP * 64) / 256, 256>>>(ymx2, ymn2, scale + 64, shift + 64, x2, 64);

    // -------- d1 branch: edge conv 64->64 on gf(x1) with idx2 --------
    proj_kernel<<<1024, 256>>>(x1, 32, 1, NN * 32, wd1, 64, 0, 32, 64, PA, Q, 0);
    edge_kernel<64, false><<<512, 256>>>(idx2, idx2, PA, PA, Q, ymxd1, ymnd1, S1 + 128, S2 + 128);
    finalize_kernel<<<1, 64>>>(S1 + 128, S2 + 128, gd1, bd1, scale + 128, shift + 128, 64);

    // -------- d2 branch: knn(x2, C=64), edge conv 128->64 --------
    norm_kernel<<<NP / 256, 256>>>(x2, 64, 1, NN * 64, 64, nrm);
    knn_part<64><<<kgrid, 128>>>(x2, 64, 1, NN * 64, nrm, pv, pi);
    knn_merge<<<NP / 256, 256>>>(pv, pi, idx3);
    proj_kernel<<<1024, 256>>>(x2, 64, 1, NN * 64, wd2, 128, 0, 64, 64, PA, Q, 0);
    edge_kernel<64, false><<<512, 256>>>(idx3, idx3, PA, PA, Q, ymxd2, ymnd2, S1 + 192, S2 + 192);
    finalize_kernel<<<1, 64>>>(S1 + 192, S2 + 192, gd2, bd2, scale + 192, shift + 192, 64);

    // -------- head: column mean + 3 dense layers --------
    hcol_kernel<<<NP / 4, 256>>>(ymxd1, ymnd1, ymxd2, ymnd2);
    head_kernel<<<1, 128>>>(W2d, b2d, W3d, b3d, W4d, b4d, (float*)d_out);
}

// round 15
// speedup vs baseline: 1.4086x; 1.4086x over previous
#include <cuda_runtime.h>
#include <cstdint>

// ---------------------------------------------------------------------------
// DGCNN-style net. B=8, N=4096, K=20. Output: 11 floats.
// Exact fp32. KNN: one thread per query, 2-way candidate ILP (4 independent
// FMA chains), top-20 kept in registers, emitted in jax.lax.top_k order.
// ---------------------------------------------------------------------------
#define NB 8
#define NN 4096
#define NP (NB * NN)      // 32768
#define KK 20
#define SLOPE 0.2f
#define MCNT ((double)NP * (double)KK)   // 655360 samples per BN channel

// ------------------------------ device scratch ------------------------------
__device__ int   g_idx1[NP * KK];
__device__ int   g_idx2[NP * KK];
__device__ int   g_idx3[NP * KK];
__device__ float g_nrm[NP];

__device__ float g_P1[NP * 32], g_Q1[NP * 32];
__device__ float g_ymx1[NP * 32], g_ymn1[NP * 32];
__device__ float g_x1[NP * 32];

__device__ float g_PA[NP * 64], g_PB[NP * 64], g_Q[NP * 64];
__device__ float g_ymx2[NP * 64], g_ymn2[NP * 64];
__device__ float g_x2[NP * 64];

__device__ float g_ymxd1[NP * 64], g_ymnd1[NP * 64];
__device__ float g_ymxd2[NP * 64], g_ymnd2[NP * 64];

__device__ double g_S1[256], g_S2[256];
__device__ float  g_scale[256], g_shift[256];
__device__ double g_hcol[128];

// ------------------------------ helpers -------------------------------------
__device__ __forceinline__ unsigned long long pack2(float a, float b) {
    return (unsigned long long)__float_as_uint(a) |
           ((unsigned long long)__float_as_uint(b) << 32);
}
__device__ __forceinline__ float2 unpack2(unsigned long long v) {
    float2 r;
    r.x = __uint_as_float((unsigned int)v);
    r.y = __uint_as_float((unsigned int)(v >> 32));
    return r;
}
#define FMA2(acc, a, b) \
    asm("fma.rn.f32x2 %0, %1, %2, %0;" : "+l"(acc) : "l"(a), "l"(b))

__device__ __forceinline__ float lrelu(float v) { return v >= 0.f ? v : SLOPE * v; }

// ------------------------------ zero accumulators ----------------------------
__global__ void zero_kernel() {
    int t = threadIdx.x;
    if (t < 256) { g_S1[t] = 0.0; g_S2[t] = 0.0; }
    if (t < 128) g_hcol[t] = 0.0;
}

// ------------------------------ point squared norms --------------------------
// feat(b,n,c) at feat[b*bs + n*ps + c*cs]
__global__ void norm_kernel(const float* __restrict__ feat, int ps, int cs, int bs,
                            int C, float* __restrict__ out) {
    int pt = blockIdx.x * blockDim.x + threadIdx.x;
    if (pt >= NP) return;
    int b = pt >> 12, n = pt & (NN - 1);
    const float* f = feat + (size_t)b * bs + (size_t)n * ps;
    float s = 0.f;
    for (int c = 0; c < C; c++) { float v = f[(size_t)c * cs]; s = fmaf(v, v, s); }
    out[pt] = s;
}

// ------------------------------ exact KNN, sorted output ---------------------
// rank by e = 2<q,m> - |m|^2 (same ordering as reference d per query).
// Output sorted: descending e, ascending index on ties (== jax.lax.top_k).
// 2 candidates per iteration, 4 independent FMA2 chains for ILP.
template <int C>
__global__ void __launch_bounds__(128)
knn_kernel(const float* __restrict__ feat, int ps, int cs, int bs,
           const float* __restrict__ norms, int* __restrict__ idxOut) {
    constexpr int CP = (C + 3) & ~3;
    constexpr int TILE = 128;
    __shared__ __align__(16) float st[TILE * CP];
    __shared__ float sn[TILE];

    const int b  = blockIdx.y;
    const int qn = blockIdx.x * TILE + threadIdx.x;
    const float* fb = feat + (size_t)b * bs;
    const float* nb = norms + b * NN;

    unsigned long long qp[CP / 2];
#pragma unroll
    for (int j = 0; j < CP / 2; j++) {
        float a  = (2 * j     < C) ? fb[(size_t)qn * ps + (size_t)(2 * j) * cs]     : 0.f;
        float c2 = (2 * j + 1 < C) ? fb[(size_t)qn * ps + (size_t)(2 * j + 1) * cs] : 0.f;
        qp[j] = pack2(a, c2);
    }

    const float NEGINF = __int_as_float(0xff800000);
    float kd[KK]; int ki[KK];
#pragma unroll
    for (int i = 0; i < KK; i++) { kd[i] = NEGINF; ki[i] = 0x7fffffff; }
    float curmin = NEGINF; int minpos = 0;

    auto insert = [&](float e, int m) {
#pragma unroll
        for (int i = 0; i < KK; i++)
            if (i == minpos) { kd[i] = e; ki[i] = m; }
        curmin = kd[0]; minpos = 0;
#pragma unroll
        for (int i = 1; i < KK; i++)
            if (kd[i] < curmin) { curmin = kd[i]; minpos = i; }
    };

    for (int m0 = 0; m0 < NN; m0 += TILE) {
        __syncthreads();
#pragma unroll
        for (int i = 0; i < (TILE * CP) / 128; i++) {
            int lin = threadIdx.x + i * 128;
            int m = lin / CP, c = lin % CP;
            st[lin] = (c < C) ? fb[(size_t)(m0 + m) * ps + (size_t)c * cs] : 0.f;
        }
        sn[threadIdx.x] = nb[m0 + threadIdx.x];
        __syncthreads();

#pragma unroll 1
        for (int mm = 0; mm < TILE; mm += 2) {
            unsigned long long a0 = 0ull, a1 = 0ull, b0 = 0ull, b1 = 0ull;
            const ulonglong2* sp0 = reinterpret_cast<const ulonglong2*>(st + mm * CP);
            const ulonglong2* sp1 = reinterpret_cast<const ulonglong2*>(st + mm * CP + CP);
#pragma unroll
            for (int j = 0; j < CP / 4; j++) {
                ulonglong2 v0 = sp0[j];
                ulonglong2 v1 = sp1[j];
                FMA2(a0, qp[2 * j],     v0.x);
                FMA2(a1, qp[2 * j + 1], v0.y);
                FMA2(b0, qp[2 * j],     v1.x);
                FMA2(b1, qp[2 * j + 1], v1.y);
            }
            float2 fa0 = unpack2(a0), fa1 = unpack2(a1);
            float2 fb0 = unpack2(b0), fb1 = unpack2(b1);
            float e0 = fmaf(2.f, (fa0.x + fa0.y) + (fa1.x + fa1.y), -sn[mm]);
            float e1 = fmaf(2.f, (fb0.x + fb0.y) + (fb1.x + fb1.y), -sn[mm + 1]);
            if (e0 > curmin) insert(e0, m0 + mm);       // strict > : low idx wins ties
            if (e1 > curmin) insert(e1, m0 + mm + 1);
        }
    }

    // Sort: descending value, ascending index on ties (top_k order).
#pragma unroll
    for (int i = 0; i < KK - 1; i++)
#pragma unroll
        for (int j = i + 1; j < KK; j++) {
            bool sw = (kd[j] > kd[i]) || (kd[j] == kd[i] && ki[j] < ki[i]);
            float td = sw ? kd[j] : kd[i];
            int   ti = sw ? ki[j] : ki[i];
            kd[j] = sw ? kd[i] : kd[j];
            ki[j] = sw ? ki[i] : ki[j];
            kd[i] = td; ki[i] = ti;
        }

    int* op = idxOut + (size_t)(b * NN + qn) * KK;
#pragma unroll
    for (int i = 0; i < KK; i++) op[i] = ki[i];
}

// ------------------------------ per-point projections ------------------------
// P[pt][o] = sum_c w[o][wcol+c]              * feat(pt,c)   (neighbor term)
// Q[pt][o] = sum_c (w[o][wcol+C+c]-w[o][wcol+c]) * feat(pt,c)  (+= if accumQ)
__global__ void proj_kernel(const float* __restrict__ feat, int ps, int cs, int bs,
                            const float* __restrict__ w, int wld, int wcol,
                            int C, int O,
                            float* __restrict__ P, float* __restrict__ Q, int accumQ) {
    __shared__ float wa[64 * 64];
    __shared__ float wb[64 * 64];
    for (int lin = threadIdx.x; lin < O * C; lin += blockDim.x) {
        int o = lin / C, c = lin % C;
        float a  = w[o * wld + wcol + c];
        float b2 = w[o * wld + wcol + C + c];
        wa[c * 64 + o] = a;
        wb[c * 64 + o] = b2 - a;
    }
    __syncthreads();
    int o    = threadIdx.x % O;
    int sub  = threadIdx.x / O;
    int subs = blockDim.x / O;
    for (int pt = blockIdx.x * subs + sub; pt < NP; pt += gridDim.x * subs) {
        int b = pt >> 12, n = pt & (NN - 1);
        const float* f = feat + (size_t)b * bs + (size_t)n * ps;
        float ap = 0.f, aq = 0.f;
        for (int c = 0; c < C; c++) {
            float v = __ldg(f + (size_t)c * cs);
            ap = fmaf(wa[c * 64 + o], v, ap);
            aq = fmaf(wb[c * 64 + o], v, aq);
        }
        P[(size_t)pt * O + o] = ap;
        if (accumQ) Q[(size_t)pt * O + o] += aq;
        else        Q[(size_t)pt * O + o]  = aq;
    }
}

// ------------------------------ edge pass ------------------------------------
// y(pt,o,k) = PA[idxA[k]] (+ PB[idxB[k]]) + Q[pt]; k-th entries paired.
template <int O, bool DUAL>
__global__ void edge_kernel(const int* __restrict__ idxA, const int* __restrict__ idxB,
                            const float* __restrict__ PA, const float* __restrict__ PB,
                            const float* __restrict__ Q,
                            float* __restrict__ YMAX, float* __restrict__ YMIN,
                            double* __restrict__ S1, double* __restrict__ S2) {
    const int t = threadIdx.x;
    const int o = t % O, sub = t / O;
    const int subs = blockDim.x / O;
    const float PINF = __int_as_float(0x7f800000);
    double ds1 = 0.0, ds2 = 0.0;

    for (int pt = blockIdx.x * subs + sub; pt < NP; pt += gridDim.x * subs) {
        const int pbase = pt & ~(NN - 1);
        const int* iA = idxA + (size_t)pt * KK;
        const int* iB = idxB + (size_t)pt * KK;
        float qv = Q[(size_t)pt * O + o];
        float vmax = -PINF, vmin = PINF;
        float ls1 = 0.f, ls2 = 0.f;
#pragma unroll
        for (int k = 0; k < KK; k++) {
            int jA = __ldg(iA + k);
            float v = __ldg(PA + (size_t)(pbase + jA) * O + o);
            if (DUAL) {
                int jB = __ldg(iB + k);
                v += __ldg(PB + (size_t)(pbase + jB) * O + o);
            }
            vmax = fmaxf(vmax, v);
            vmin = fminf(vmin, v);
            float y = v + qv;
            ls1 += y;
            ls2 = fmaf(y, y, ls2);
        }
        YMAX[(size_t)pt * O + o] = vmax + qv;
        YMIN[(size_t)pt * O + o] = vmin + qv;
        ds1 += (double)ls1;
        ds2 += (double)ls2;
    }

    __shared__ double r1[256], r2[256];
    r1[t] = ds1; r2[t] = ds2;
    __syncthreads();
    if (sub == 0) {
        double a = ds1, b2 = ds2;
        for (int s = 1; s < subs; s++) { a += r1[s * O + o]; b2 += r2[s * O + o]; }
        atomicAdd(&S1[o], a);
        atomicAdd(&S2[o], b2);
    }
}

// ------------------------------ BN finalize ----------------------------------
__global__ void finalize_kernel(const double* __restrict__ S1, const double* __restrict__ S2,
                                const float* __restrict__ g, const float* __restrict__ beta,
                                float* __restrict__ scale, float* __restrict__ shift, int O) {
    int o = threadIdx.x;
    if (o >= O) return;
    double mean = S1[o] / MCNT;
    double var  = S2[o] / MCNT - mean * mean;
    double inv  = 1.0 / sqrt(var + 1e-5);
    double sc   = (double)g[o] * inv;
    scale[o] = (float)sc;
    shift[o] = (float)((double)beta[o] - mean * sc);
}

// ------------------------------ apply affine+lrelu to pooled extremum --------
__global__ void apply_kernel(const float* __restrict__ YMAX, const float* __restrict__ YMIN,
                             const float* __restrict__ scale, const float* __restrict__ shift,
                             float* __restrict__ out, int O) {
    int idx = blockIdx.x * blockDim.x + threadIdx.x;
    int o = idx % O;
    float s = scale[o];
    float z = (s >= 0.f) ? YMAX[idx] : YMIN[idx];
    out[idx] = lrelu(fmaf(s, z, shift[o]));
}

// ------------------------------ column sums for the head ---------------------
__global__ void hcol_kernel(const float* __restrict__ mx1, const float* __restrict__ mn1,
                            const float* __restrict__ mx2, const float* __restrict__ mn2) {
    __shared__ float red[256];
    int t = threadIdx.x, o = t & 63, p = t >> 6;
    int pt = blockIdx.x * 4 + p;
    size_t base = (size_t)pt * 64 + o;

    float s1 = g_scale[128 + o], sh1 = g_shift[128 + o];
    float z1 = (s1 >= 0.f) ? mx1[base] : mn1[base];
    float v1 = lrelu(fmaf(s1, z1, sh1));

    float s2 = g_scale[192 + o], sh2 = g_shift[192 + o];
    float z2 = (s2 >= 0.f) ? mx2[base] : mn2[base];
    float v2 = lrelu(fmaf(s2, z2, sh2));

    red[t] = v1 + v2;
    __syncthreads();
    if (o == 0) {
        float s = 0.f;
        for (int j = 0; j < 64; j++) s += red[p * 64 + j];
        atomicAdd(&g_hcol[pt & 127], (double)s);
    }
}

// ------------------------------ tiny MLP head --------------------------------
__global__ void head_kernel(const float* __restrict__ W2d, const float* __restrict__ b2d,
                            const float* __restrict__ W3d, const float* __restrict__ b3d,
                            const float* __restrict__ W4d, const float* __restrict__ b4d,
                            float* __restrict__ out) {
    __shared__ float hm[128], h1[128], h2[64];
    int t = threadIdx.x;
    hm[t] = (float)(g_hcol[t] * (1.0 / 32768.0));
    __syncthreads();
    {
        float a = b2d[t];
        for (int i = 0; i < 128; i++) a = fmaf(W2d[t * 128 + i], hm[i], a);
        h1[t] = lrelu(a);
    }
    __syncthreads();
    if (t < 64) {
        float a = b3d[t];
        for (int i = 0; i < 128; i++) a = fmaf(W3d[t * 128 + i], h1[i], a);
        h2[t] = lrelu(a);
    }
    __syncthreads();
    if (t < 11) {
        float a = b4d[t];
        for (int i = 0; i < 64; i++) a = fmaf(W4d[t * 64 + i], h2[i], a);
        out[t] = lrelu(a);
    }
}

// ------------------------------ launch ---------------------------------------
extern "C" void kernel_launch(void* const* d_in, const int* in_sizes, int n_in,
                              void* d_out, int out_size) {
    const float* x   = (const float*)d_in[0];
    const float* w1  = (const float*)d_in[1];
    const float* g1  = (const float*)d_in[2];
    const float* b1  = (const float*)d_in[3];
    const float* w2  = (const float*)d_in[4];
    const float* g2  = (const float*)d_in[5];
    const float* b2  = (const float*)d_in[6];
    const float* wd1 = (const float*)d_in[7];
    const float* gd1 = (const float*)d_in[8];
    const float* bd1 = (const float*)d_in[9];
    const float* wd2 = (const float*)d_in[10];
    const float* gd2 = (const float*)d_in[11];
    const float* bd2 = (const float*)d_in[12];
    const float* W2d = (const float*)d_in[13];
    const float* b2d = (const float*)d_in[14];
    const float* W3d = (const float*)d_in[15];
    const float* b3d = (const float*)d_in[16];
    const float* W4d = (const float*)d_in[17];
    const float* b4d = (const float*)d_in[18];

    int*    idx1;  cudaGetSymbolAddress((void**)&idx1,  g_idx1);
    int*    idx2;  cudaGetSymbolAddress((void**)&idx2,  g_idx2);
    int*    idx3;  cudaGetSymbolAddress((void**)&idx3,  g_idx3);
    float*  nrm;   cudaGetSymbolAddress((void**)&nrm,   g_nrm);
    float*  P1;    cudaGetSymbolAddress((void**)&P1,    g_P1);
    float*  Q1;    cudaGetSymbolAddress((void**)&Q1,    g_Q1);
    float*  ymx1;  cudaGetSymbolAddress((void**)&ymx1,  g_ymx1);
    float*  ymn1;  cudaGetSymbolAddress((void**)&ymn1,  g_ymn1);
    float*  x1;    cudaGetSymbolAddress((void**)&x1,    g_x1);
    float*  PA;    cudaGetSymbolAddress((void**)&PA,    g_PA);
    float*  PB;    cudaGetSymbolAddress((void**)&PB,    g_PB);
    float*  Q;     cudaGetSymbolAddress((void**)&Q,     g_Q);
    float*  ymx2;  cudaGetSymbolAddress((void**)&ymx2,  g_ymx2);
    float*  ymn2;  cudaGetSymbolAddress((void**)&ymn2,  g_ymn2);
    float*  x2;    cudaGetSymbolAddress((void**)&x2,    g_x2);
    float*  ymxd1; cudaGetSymbolAddress((void**)&ymxd1, g_ymxd1);
    float*  ymnd1; cudaGetSymbolAddress((void**)&ymnd1, g_ymnd1);
    float*  ymxd2; cudaGetSymbolAddress((void**)&ymxd2, g_ymxd2);
    float*  ymnd2; cudaGetSymbolAddress((void**)&ymnd2, g_ymnd2);
    double* S1;    cudaGetSymbolAddress((void**)&S1,    g_S1);
    double* S2;    cudaGetSymbolAddress((void**)&S2,    g_S2);
    float*  scale; cudaGetSymbolAddress((void**)&scale, g_scale);
    float*  shift; cudaGetSymbolAddress((void**)&shift, g_shift);

    const dim3 kgrid(NN / 128, NB);

    zero_kernel<<<1, 256>>>();

    // -------- layer 1: knn(x, C=3), edge conv 6->32 --------
    norm_kernel<<<NP / 256, 256>>>(x, 1, NN, 3 * NN, 3, nrm);
    knn_kernel<3><<<kgrid, 128>>>(x, 1, NN, 3 * NN, nrm, idx1);
    proj_kernel<<<1024, 256>>>(x, 1, NN, 3 * NN, w1, 6, 0, 3, 32, P1, Q1, 0);
    edge_kernel<32, false><<<512, 256>>>(idx1, idx1, P1, P1, Q1, ymx1, ymn1, S1 + 0, S2 + 0);
    finalize_kernel<<<1, 32>>>(S1 + 0, S2 + 0, g1, b1, scale + 0, shift + 0, 32);
    apply_kernel<<<(NP * 32) / 256, 256>>>(ymx1, ymn1, scale + 0, shift + 0, x1, 32);

    // -------- layer 2: knn(x1, C=32), edge conv 70->64 (paired dual gather) --
    norm_kernel<<<NP / 256, 256>>>(x1, 32, 1, NN * 32, 32, nrm);
    knn_kernel<32><<<kgrid, 128>>>(x1, 32, 1, NN * 32, nrm, idx2);
    proj_kernel<<<1024, 256>>>(x, 1, NN, 3 * NN, w2, 70, 0, 3, 64, PA, Q, 0);
    proj_kernel<<<1024, 256>>>(x1, 32, 1, NN * 32, w2, 70, 6, 32, 64, PB, Q, 1);
    edge_kernel<64, true><<<512, 256>>>(idx1, idx2, PA, PB, Q, ymx2, ymn2, S1 + 64, S2 + 64);
    finalize_kernel<<<1, 64>>>(S1 + 64, S2 + 64, g2, b2, scale + 64, shift + 64, 64);
    apply_kernel<<<(NP * 64) / 256, 256>>>(ymx2, ymn2, scale + 64, shift + 64, x2, 64);

    // -------- d1 branch: edge conv 64->64 on gf(x1) with idx2 --------
    proj_kernel<<<1024, 256>>>(x1, 32, 1, NN * 32, wd1, 64, 0, 32, 64, PA, Q, 0);
    edge_kernel<64, false><<<512, 256>>>(idx2, idx2, PA, PA, Q, ymxd1, ymnd1, S1 + 128, S2 + 128);
    finalize_kernel<<<1, 64>>>(S1 + 128, S2 + 128, gd1, bd1, scale + 128, shift + 128, 64);

    // -------- d2 branch: knn(x2, C=64), edge conv 128->64 --------
    norm_kernel<<<NP / 256, 256>>>(x2, 64, 1, NN * 64, 64, nrm);
    knn_kernel<64><<<kgrid, 128>>>(x2, 64, 1, NN * 64, nrm, idx3);
    proj_kernel<<<1024, 256>>>(x2, 64, 1, NN * 64, wd2, 128, 0, 64, 64, PA, Q, 0);
    edge_kernel<64, false><<<512, 256>>>(idx3, idx3, PA, PA, Q, ymxd2, ymnd2, S1 + 192, S2 + 192);
    finalize_kernel<<<1, 64>>>(S1 + 192, S2 + 192, gd2, bd2, scale + 192, shift + 192, 64);

    // -------- head: column mean + 3 dense layers --------
    hcol_kernel<<<NP / 4, 256>>>(ymxd1, ymnd1, ymxd2, ymnd2);
    head_kernel<<<1, 128>>>(W2d, b2d, W3d, b3d, W4d, b4d, (float*)d_out);
}

// round 16
// speedup vs baseline: 1.4102x; 1.0011x over previous
#include <cuda_runtime.h>
#include <cstdint>

// ---------------------------------------------------------------------------
// DGCNN-style net. B=8, N=4096, K=20. Output: 11 floats.
// Exact fp32. KNN: one thread per query, 2-way candidate ILP (4 independent
// FMA chains), top-20 kept in registers, emitted in jax.lax.top_k order.
// ---------------------------------------------------------------------------
#define NB 8
#define NN 4096
#define NP (NB * NN)      // 32768
#define KK 20
#define SLOPE 0.2f
#define MCNT ((double)NP * (double)KK)   // 655360 samples per BN channel

// ------------------------------ device scratch ------------------------------
__device__ int   g_idx1[NP * KK];
__device__ int   g_idx2[NP * KK];
__device__ int   g_idx3[NP * KK];
__device__ float g_nrm[NP];

__device__ float g_P1[NP * 32], g_Q1[NP * 32];
__device__ float g_ymx1[NP * 32], g_ymn1[NP * 32];
__device__ float g_x1[NP * 32];

__device__ float g_PA[NP * 64], g_PB[NP * 64], g_Q[NP * 64];
__device__ float g_ymx2[NP * 64], g_ymn2[NP * 64];
__device__ float g_x2[NP * 64];

__device__ float g_ymxd1[NP * 64], g_ymnd1[NP * 64];
__device__ float g_ymxd2[NP * 64], g_ymnd2[NP * 64];

__device__ double g_S1[256], g_S2[256];
__device__ float  g_scale[256], g_shift[256];
__device__ double g_hcol[128];

// ------------------------------ helpers -------------------------------------
__device__ __forceinline__ unsigned long long pack2(float a, float b) {
    return (unsigned long long)__float_as_uint(a) |
           ((unsigned long long)__float_as_uint(b) << 32);
}
__device__ __forceinline__ float2 unpack2(unsigned long long v) {
    float2 r;
    r.x = __uint_as_float((unsigned int)v);
    r.y = __uint_as_float((unsigned int)(v >> 32));
    return r;
}
#define FMA2(acc, a, b) \
    asm("fma.rn.f32x2 %0, %1, %2, %0;" : "+l"(acc) : "l"(a), "l"(b))

__device__ __forceinline__ float lrelu(float v) { return v >= 0.f ? v : SLOPE * v; }

// ------------------------------ zero accumulators ----------------------------
__global__ void zero_kernel() {
    int t = threadIdx.x;
    if (t < 256) { g_S1[t] = 0.0; g_S2[t] = 0.0; }
    if (t < 128) g_hcol[t] = 0.0;
}

// ------------------------------ point squared norms --------------------------
// feat(b,n,c) at feat[b*bs + n*ps + c*cs]
__global__ void norm_kernel(const float* __restrict__ feat, int ps, int cs, int bs,
                            int C, float* __restrict__ out) {
    int pt = blockIdx.x * blockDim.x + threadIdx.x;
    if (pt >= NP) return;
    int b = pt >> 12, n = pt & (NN - 1);
    const float* f = feat + (size_t)b * bs + (size_t)n * ps;
    float s = 0.f;
    for (int c = 0; c < C; c++) { float v = f[(size_t)c * cs]; s = fmaf(v, v, s); }
    out[pt] = s;
}

// ------------------------------ exact KNN, sorted output ---------------------
// rank by e = 2<q,m> - |m|^2 (same ordering as reference d per query).
// Output sorted: descending e, ascending index on ties (== jax.lax.top_k).
// 2 candidates per iteration, 4 independent FMA2 chains for ILP.
template <int C>
__global__ void __launch_bounds__(128)
knn_kernel(const float* __restrict__ feat, int ps, int cs, int bs,
           const float* __restrict__ norms, int* __restrict__ idxOut) {
    constexpr int CP = (C + 3) & ~3;
    constexpr int TILE = 128;
    __shared__ __align__(16) float st[TILE * CP];
    __shared__ float sn[TILE];

    const int b  = blockIdx.y;
    const int qn = blockIdx.x * TILE + threadIdx.x;
    const float* fb = feat + (size_t)b * bs;
    const float* nb = norms + b * NN;

    unsigned long long qp[CP / 2];
#pragma unroll
    for (int j = 0; j < CP / 2; j++) {
        float a  = (2 * j     < C) ? fb[(size_t)qn * ps + (size_t)(2 * j) * cs]     : 0.f;
        float c2 = (2 * j + 1 < C) ? fb[(size_t)qn * ps + (size_t)(2 * j + 1) * cs] : 0.f;
        qp[j] = pack2(a, c2);
    }

    const float NEGINF = __int_as_float(0xff800000);
    float kd[KK]; int ki[KK];
#pragma unroll
    for (int i = 0; i < KK; i++) { kd[i] = NEGINF; ki[i] = 0x7fffffff; }
    float curmin = NEGINF; int minpos = 0;

    auto insert = [&](float e, int m) {
#pragma unroll
        for (int i = 0; i < KK; i++)
            if (i == minpos) { kd[i] = e; ki[i] = m; }
        curmin = kd[0]; minpos = 0;
#pragma unroll
        for (int i = 1; i < KK; i++)
            if (kd[i] < curmin) { curmin = kd[i]; minpos = i; }
    };

    for (int m0 = 0; m0 < NN; m0 += TILE) {
        __syncthreads();
#pragma unroll
        for (int i = 0; i < (TILE * CP) / 128; i++) {
            int lin = threadIdx.x + i * 128;
            int m = lin / CP, c = lin % CP;
            st[lin] = (c < C) ? fb[(size_t)(m0 + m) * ps + (size_t)c * cs] : 0.f;
        }
        sn[threadIdx.x] = nb[m0 + threadIdx.x];
        __syncthreads();

#pragma unroll 1
        for (int mm = 0; mm < TILE; mm += 2) {
            unsigned long long a0 = 0ull, a1 = 0ull, b0 = 0ull, b1 = 0ull;
            const ulonglong2* sp0 = reinterpret_cast<const ulonglong2*>(st + mm * CP);
            const ulonglong2* sp1 = reinterpret_cast<const ulonglong2*>(st + mm * CP + CP);
#pragma unroll
            for (int j = 0; j < CP / 4; j++) {
                ulonglong2 v0 = sp0[j];
                ulonglong2 v1 = sp1[j];
                FMA2(a0, qp[2 * j],     v0.x);
                FMA2(a1, qp[2 * j + 1], v0.y);
                FMA2(b0, qp[2 * j],     v1.x);
                FMA2(b1, qp[2 * j + 1], v1.y);
            }
            float2 fa0 = unpack2(a0), fa1 = unpack2(a1);
            float2 fb0 = unpack2(b0), fb1 = unpack2(b1);
            float e0 = fmaf(2.f, (fa0.x + fa0.y) + (fa1.x + fa1.y), -sn[mm]);
            float e1 = fmaf(2.f, (fb0.x + fb0.y) + (fb1.x + fb1.y), -sn[mm + 1]);
            if (e0 > curmin) insert(e0, m0 + mm);       // strict > : low idx wins ties
            if (e1 > curmin) insert(e1, m0 + mm + 1);
        }
    }

    // Sort: descending value, ascending index on ties (top_k order).
#pragma unroll
    for (int i = 0; i < KK - 1; i++)
#pragma unroll
        for (int j = i + 1; j < KK; j++) {
            bool sw = (kd[j] > kd[i]) || (kd[j] == kd[i] && ki[j] < ki[i]);
            float td = sw ? kd[j] : kd[i];
            int   ti = sw ? ki[j] : ki[i];
            kd[j] = sw ? kd[i] : kd[j];
            ki[j] = sw ? ki[i] : ki[j];
            kd[i] = td; ki[i] = ti;
        }

    int* op = idxOut + (size_t)(b * NN + qn) * KK;
#pragma unroll
    for (int i = 0; i < KK; i++) op[i] = ki[i];
}

// ------------------------------ per-point projections ------------------------
// P[pt][o] = sum_c w[o][wcol+c]              * feat(pt,c)   (neighbor term)
// Q[pt][o] = sum_c (w[o][wcol+C+c]-w[o][wcol+c]) * feat(pt,c)  (+= if accumQ)
__global__ void proj_kernel(const float* __restrict__ feat, int ps, int cs, int bs,
                            const float* __restrict__ w, int wld, int wcol,
                            int C, int O,
                            float* __restrict__ P, float* __restrict__ Q, int accumQ) {
    __shared__ float wa[64 * 64];
    __shared__ float wb[64 * 64];
    for (int lin = threadIdx.x; lin < O * C; lin += blockDim.x) {
        int o = lin / C, c = lin % C;
        float a  = w[o * wld + wcol + c];
        float b2 = w[o * wld + wcol + C + c];
        wa[c * 64 + o] = a;
        wb[c * 64 + o] = b2 - a;
    }
    __syncthreads();
    int o    = threadIdx.x % O;
    int sub  = threadIdx.x / O;
    int subs = blockDim.x / O;
    for (int pt = blockIdx.x * subs + sub; pt < NP; pt += gridDim.x * subs) {
        int b = pt >> 12, n = pt & (NN - 1);
        const float* f = feat + (size_t)b * bs + (size_t)n * ps;
        float ap = 0.f, aq = 0.f;
        for (int c = 0; c < C; c++) {
            float v = __ldg(f + (size_t)c * cs);
            ap = fmaf(wa[c * 64 + o], v, ap);
            aq = fmaf(wb[c * 64 + o], v, aq);
        }
        P[(size_t)pt * O + o] = ap;
        if (accumQ) Q[(size_t)pt * O + o] += aq;
        else        Q[(size_t)pt * O + o]  = aq;
    }
}

// ------------------------------ edge pass ------------------------------------
// y(pt,o,k) = PA[idxA[k]] (+ PB[idxB[k]]) + Q[pt]; k-th entries paired.
template <int O, bool DUAL>
__global__ void edge_kernel(const int* __restrict__ idxA, const int* __restrict__ idxB,
                            const float* __restrict__ PA, const float* __restrict__ PB,
                            const float* __restrict__ Q,
                            float* __restrict__ YMAX, float* __restrict__ YMIN,
                            double* __restrict__ S1, double* __restrict__ S2) {
    const int t = threadIdx.x;
    const int o = t % O, sub = t / O;
    const int subs = blockDim.x / O;
    const float PINF = __int_as_float(0x7f800000);
    double ds1 = 0.0, ds2 = 0.0;

    for (int pt = blockIdx.x * subs + sub; pt < NP; pt += gridDim.x * subs) {
        const int pbase = pt & ~(NN - 1);
        const int* iA = idxA + (size_t)pt * KK;
        const int* iB = idxB + (size_t)pt * KK;
        float qv = Q[(size_t)pt * O + o];
        float vmax = -PINF, vmin = PINF;
        float ls1 = 0.f, ls2 = 0.f;
#pragma unroll
        for (int k = 0; k < KK; k++) {
            int jA = __ldg(iA + k);
            float v = __ldg(PA + (size_t)(pbase + jA) * O + o);
            if (DUAL) {
                int jB = __ldg(iB + k);
                v += __ldg(PB + (size_t)(pbase + jB) * O + o);
            }
            vmax = fmaxf(vmax, v);
            vmin = fminf(vmin, v);
            float y = v + qv;
            ls1 += y;
            ls2 = fmaf(y, y, ls2);
        }
        YMAX[(size_t)pt * O + o] = vmax + qv;
        YMIN[(size_t)pt * O + o] = vmin + qv;
        ds1 += (double)ls1;
        ds2 += (double)ls2;
    }

    __shared__ double r1[256], r2[256];
    r1[t] = ds1; r2[t] = ds2;
    __syncthreads();
    if (sub == 0) {
        double a = ds1, b2 = ds2;
        for (int s = 1; s < subs; s++) { a += r1[s * O + o]; b2 += r2[s * O + o]; }
        atomicAdd(&S1[o], a);
        atomicAdd(&S2[o], b2);
    }
}

// ------------------------------ BN finalize ----------------------------------
__global__ void finalize_kernel(const double* __restrict__ S1, const double* __restrict__ S2,
                                const float* __restrict__ g, const float* __restrict__ beta,
                                float* __restrict__ scale, float* __restrict__ shift, int O) {
    int o = threadIdx.x;
    if (o >= O) return;
    double mean = S1[o] / MCNT;
    double var  = S2[o] / MCNT - mean * mean;
    double inv  = 1.0 / sqrt(var + 1e-5);
    double sc   = (double)g[o] * inv;
    scale[o] = (float)sc;
    shift[o] = (float)((double)beta[o] - mean * sc);
}

// ------------------------------ apply affine+lrelu to pooled extremum --------
__global__ void apply_kernel(const float* __restrict__ YMAX, const float* __restrict__ YMIN,
                             const float* __restrict__ scale, const float* __restrict__ shift,
                             float* __restrict__ out, int O) {
    int idx = blockIdx.x * blockDim.x + threadIdx.x;
    int o = idx % O;
    float s = scale[o];
    float z = (s >= 0.f) ? YMAX[idx] : YMIN[idx];
    out[idx] = lrelu(fmaf(s, z, shift[o]));
}

// ------------------------------ column sums for the head ---------------------
__global__ void hcol_kernel(const float* __restrict__ mx1, const float* __restrict__ mn1,
                            const float* __restrict__ mx2, const float* __restrict__ mn2) {
    __shared__ float red[256];
    int t = threadIdx.x, o = t & 63, p = t >> 6;
    int pt = blockIdx.x * 4 + p;
    size_t base = (size_t)pt * 64 + o;

    float s1 = g_scale[128 + o], sh1 = g_shift[128 + o];
    float z1 = (s1 >= 0.f) ? mx1[base] : mn1[base];
    float v1 = lrelu(fmaf(s1, z1, sh1));

    float s2 = g_scale[192 + o], sh2 = g_shift[192 + o];
    float z2 = (s2 >= 0.f) ? mx2[base] : mn2[base];
    float v2 = lrelu(fmaf(s2, z2, sh2));

    red[t] = v1 + v2;
    __syncthreads();
    if (o == 0) {
        float s = 0.f;
        for (int j = 0; j < 64; j++) s += red[p * 64 + j];
        atomicAdd(&g_hcol[pt & 127], (double)s);
    }
}

// ------------------------------ tiny MLP head --------------------------------
__global__ void head_kernel(const float* __restrict__ W2d, const float* __restrict__ b2d,
                            const float* __restrict__ W3d, const float* __restrict__ b3d,
                            const float* __restrict__ W4d, const float* __restrict__ b4d,
                            float* __restrict__ out) {
    __shared__ float hm[128], h1[128], h2[64];
    int t = threadIdx.x;
    hm[t] = (float)(g_hcol[t] * (1.0 / 32768.0));
    __syncthreads();
    {
        float a = b2d[t];
        for (int i = 0; i < 128; i++) a = fmaf(W2d[t * 128 + i], hm[i], a);
        h1[t] = lrelu(a);
    }
    __syncthreads();
    if (t < 64) {
        float a = b3d[t];
        for (int i = 0; i < 128; i++) a = fmaf(W3d[t * 128 + i], h1[i], a);
        h2[t] = lrelu(a);
    }
    __syncthreads();
    if (t < 11) {
        float a = b4d[t];
        for (int i = 0; i < 64; i++) a = fmaf(W4d[t * 64 + i], h2[i], a);
        out[t] = lrelu(a);
    }
}

// ------------------------------ launch ---------------------------------------
extern "C" void kernel_launch(void* const* d_in, const int* in_sizes, int n_in,
                              void* d_out, int out_size) {
    const float* x   = (const float*)d_in[0];
    const float* w1  = (const float*)d_in[1];
    const float* g1  = (const float*)d_in[2];
    const float* b1  = (const float*)d_in[3];
    const float* w2  = (const float*)d_in[4];
    const float* g2  = (const float*)d_in[5];
    const float* b2  = (const float*)d_in[6];
    const float* wd1 = (const float*)d_in[7];
    const float* gd1 = (const float*)d_in[8];
    const float* bd1 = (const float*)d_in[9];
    const float* wd2 = (const float*)d_in[10];
    const float* gd2 = (const float*)d_in[11];
    const float* bd2 = (const float*)d_in[12];
    const float* W2d = (const float*)d_in[13];
    const float* b2d = (const float*)d_in[14];
    const float* W3d = (const float*)d_in[15];
    const float* b3d = (const float*)d_in[16];
    const float* W4d = (const float*)d_in[17];
    const float* b4d = (const float*)d_in[18];

    int*    idx1;  cudaGetSymbolAddress((void**)&idx1,  g_idx1);
    int*    idx2;  cudaGetSymbolAddress((void**)&idx2,  g_idx2);
    int*    idx3;  cudaGetSymbolAddress((void**)&idx3,  g_idx3);
    float*  nrm;   cudaGetSymbolAddress((void**)&nrm,   g_nrm);
    float*  P1;    cudaGetSymbolAddress((void**)&P1,    g_P1);
    float*  Q1;    cudaGetSymbolAddress((void**)&Q1,    g_Q1);
    float*  ymx1;  cudaGetSymbolAddress((void**)&ymx1,  g_ymx1);
    float*  ymn1;  cudaGetSymbolAddress((void**)&ymn1,  g_ymn1);
    float*  x1;    cudaGetSymbolAddress((void**)&x1,    g_x1);
    float*  PA;    cudaGetSymbolAddress((void**)&PA,    g_PA);
    float*  PB;    cudaGetSymbolAddress((void**)&PB,    g_PB);
    float*  Q;     cudaGetSymbolAddress((void**)&Q,     g_Q);
    float*  ymx2;  cudaGetSymbolAddress((void**)&ymx2,  g_ymx2);
    float*  ymn2;  cudaGetSymbolAddress((void**)&ymn2,  g_ymn2);
    float*  x2;    cudaGetSymbolAddress((void**)&x2,    g_x2);
    float*  ymxd1; cudaGetSymbolAddress((void**)&ymxd1, g_ymxd1);
    float*  ymnd1; cudaGetSymbolAddress((void**)&ymnd1, g_ymnd1);
    float*  ymxd2; cudaGetSymbolAddress((void**)&ymxd2, g_ymxd2);
    float*  ymnd2; cudaGetSymbolAddress((void**)&ymnd2, g_ymnd2);
    double* S1;    cudaGetSymbolAddress((void**)&S1,    g_S1);
    double* S2;    cudaGetSymbolAddress((void**)&S2,    g_S2);
    float*  scale; cudaGetSymbolAddress((void**)&scale, g_scale);
    float*  shift; cudaGetSymbolAddress((void**)&shift, g_shift);

    const dim3 kgrid(NN / 128, NB);

    zero_kernel<<<1, 256>>>();

    // -------- layer 1: knn(x, C=3), edge conv 6->32 --------
    norm_kernel<<<NP / 256, 256>>>(x, 1, NN, 3 * NN, 3, nrm);
    knn_kernel<3><<<kgrid, 128>>>(x, 1, NN, 3 * NN, nrm, idx1);
    proj_kernel<<<1024, 256>>>(x, 1, NN, 3 * NN, w1, 6, 0, 3, 32, P1, Q1, 0);
    edge_kernel<32, false><<<512, 256>>>(idx1, idx1, P1, P1, Q1, ymx1, ymn1, S1 + 0, S2 + 0);
    finalize_kernel<<<1, 32>>>(S1 + 0, S2 + 0, g1, b1, scale + 0, shift + 0, 32);
    apply_kernel<<<(NP * 32) / 256, 256>>>(ymx1, ymn1, scale + 0, shift + 0, x1, 32);

    // -------- layer 2: knn(x1, C=32), edge conv 70->64 (paired dual gather) --
    norm_kernel<<<NP / 256, 256>>>(x1, 32, 1, NN * 32, 32, nrm);
    knn_kernel<32><<<kgrid, 128>>>(x1, 32, 1, NN * 32, nrm, idx2);
    proj_kernel<<<1024, 256>>>(x, 1, NN, 3 * NN, w2, 70, 0, 3, 64, PA, Q, 0);
    proj_kernel<<<1024, 256>>>(x1, 32, 1, NN * 32, w2, 70, 6, 32, 64, PB, Q, 1);
    edge_kernel<64, true><<<512, 256>>>(idx1, idx2, PA, PB, Q, ymx2, ymn2, S1 + 64, S2 + 64);
    finalize_kernel<<<1, 64>>>(S1 + 64, S2 + 64, g2, b2, scale + 64, shift + 64, 64);
    apply_kernel<<<(NP * 64) / 256, 256>>>(ymx2, ymn2, scale + 64, shift + 64, x2, 64);

    // -------- d1 branch: edge conv 64->64 on gf(x1) with idx2 --------
    proj_kernel<<<1024, 256>>>(x1, 32, 1, NN * 32, wd1, 64, 0, 32, 64, PA, Q, 0);
    edge_kernel<64, false><<<512, 256>>>(idx2, idx2, PA, PA, Q, ymxd1, ymnd1, S1 + 128, S2 + 128);
    finalize_kernel<<<1, 64>>>(S1 + 128, S2 + 128, gd1, bd1, scale + 128, shift + 128, 64);

    // -------- d2 branch: knn(x2, C=64), edge conv 128->64 --------
    norm_kernel<<<NP / 256, 256>>>(x2, 64, 1, NN * 64, 64, nrm);
    knn_kernel<64><<<kgrid, 128>>>(x2, 64, 1, NN * 64, nrm, idx3);
    proj_kernel<<<1024, 256>>>(x2, 64, 1, NN * 64, wd2, 128, 0, 64, 64, PA, Q, 0);
    edge_kernel<64, false><<<512, 256>>>(idx3, idx3, PA, PA, Q, ymxd2, ymnd2, S1 + 192, S2 + 192);
    finalize_kernel<<<1, 64>>>(S1 + 192, S2 + 192, gd2, bd2, scale + 192, shift + 192, 64);

    // -------- head: column mean + 3 dense layers --------
    hcol_kernel<<<NP / 4, 256>>>(ymxd1, ymnd1, ymxd2, ymnd2);
    head_kernel<<<1, 128>>>(W2d, b2d, W3d, b3d, W4d, b4d, (float*)d_out);
}